// round 15
// baseline (speedup 1.0000x reference)
#include <cuda_runtime.h>
#include <cuda_bf16.h>
#include <cstdint>

// Problem shapes (fixed by the dataset)
#define B_DIM 32
#define S_DIM 1024
#define H_DIM 384
#define MAXLEN 8192

// Output layout (flattened tuple, return order):
//   [0, B*MAXLEN*H)                      : out (float32)
//   [B*MAXLEN*H, +B)                     : mel_len (as float32)
//   [B*MAXLEN*H + B, +B*MAXLEN)          : mel_mask (as float32)
#define OFF_LEN   ((long long)B_DIM * MAXLEN * H_DIM)
#define OFF_MASK  (OFF_LEN + B_DIM)

#define FRAMES_PER_BLOCK 16
#define BLOCKS_PER_BATCH (MAXLEN / FRAMES_PER_BLOCK)   // 512

// Scratch (no cudaMalloc allowed)
__device__ int g_cum[B_DIM * S_DIM];      // inclusive cumsum of durations

// ---------------------------------------------------------------------------
// Kernel 1: per-batch inclusive scan only (128 KB out) + mel_len.
// ---------------------------------------------------------------------------
__global__ void __launch_bounds__(1024) k_scan(
        const int* __restrict__ dur,
        float* __restrict__ out) {
    const int b   = blockIdx.x;
    const int tid = threadIdx.x;          // 0..1023

    __shared__ int s_warp[32];

    int v = dur[b * S_DIM + tid];

    const int lane = tid & 31;
    const int wid  = tid >> 5;
    #pragma unroll
    for (int d = 1; d < 32; d <<= 1) {
        int n = __shfl_up_sync(0xffffffffu, v, d);
        if (lane >= d) v += n;
    }
    if (lane == 31) s_warp[wid] = v;
    __syncthreads();

    if (wid == 0) {
        int w = s_warp[lane];
        #pragma unroll
        for (int d = 1; d < 32; d <<= 1) {
            int n = __shfl_up_sync(0xffffffffu, w, d);
            if (lane >= d) w += n;
        }
        s_warp[lane] = w;
    }
    __syncthreads();

    if (wid > 0) v += s_warp[wid - 1];
    g_cum[b * S_DIM + tid] = v;

    if (tid == S_DIM - 1)
        out[OFF_LEN + b] = (float)v;      // mel_len output (float32)
}

// ---------------------------------------------------------------------------
// Kernel 2: fused index + gather + mask. 16 frames per block, 4 float4 per
// thread (MLP=4 -- the config that measured 70.9us; MLP8 was neutral).
// blockDim = 384, grid = 16384.
//   - stage the batch's 4 KB cum row into shared (g_cum is L2-resident)
//   - ONE sync; then EVERY thread does its own 4 upper_bounds (LDS broadcast
//     within each 96-lane frame group) -- no warp0 serialization, no 2nd sync
//     (R14: warp0-serial search + double sync cost ~1.3us on the gather)
//   - 4 independent gathers, evict-first stores
//
// NOTE 1: upper_bound over 1024 elements has 1025 possible results -> needs
// ceil(log2(1025)) = 11 comparisons (10 was the R1-R5 rel_err=4e-2 bug).
// NOTE 2: bool inputs are stored as int32 by the harness (R6 fingerprint:
// rel_err = sqrt(3)/2). Read masks as const int*.
// ---------------------------------------------------------------------------
__global__ void __launch_bounds__(384) k_gather(const float4* __restrict__ x4,
                                                const int* __restrict__ mel_mask,
                                                float4* __restrict__ out4,
                                                float* __restrict__ out) {
    const int tid = threadIdx.x;
    const int b   = blockIdx.x / BLOCKS_PER_BATCH;
    const int t0  = (blockIdx.x % BLOCKS_PER_BATCH) * FRAMES_PER_BLOCK;

    __shared__ int s_cum[S_DIM];

    // stage cum row: 1024 ints over 384 threads (3 strided passes)
    #pragma unroll
    for (int i = tid; i < S_DIM; i += 384)
        s_cum[i] = g_cum[b * S_DIM + i];
    __syncthreads();

    const int fl   = tid / 96;                  // frame slot (0..3)
    const int lane = tid - fl * 96;             // float4 lane (0..95)
    const int mel_len = s_cum[S_DIM - 1];

    // per-thread searchsorted for its 4 frames (t = t0 + fl + 4i)
    int idx[4];
    #pragma unroll
    for (int i = 0; i < 4; ++i) {
        const int t = t0 + fl + i * 4;
        int lo = 0, hi = S_DIM;
        #pragma unroll
        for (int k = 0; k < 11; ++k) {
            if (lo < hi) {
                int mid = (lo + hi) >> 1;
                if (s_cum[mid] <= t) lo = mid + 1; else hi = mid;
            }
        }
        int id = lo < S_DIM ? lo : S_DIM - 1;
        idx[i] = (t < mel_len) ? id : -1;
    }

    const long long xbase = (long long)(b << 10) * 96;           // S=2^10
    const long long obase = ((long long)b * MAXLEN + t0) * 96;

    float4 v[4];
    #pragma unroll
    for (int i = 0; i < 4; ++i) {
        v[i] = make_float4(0.f, 0.f, 0.f, 0.f);
        if (idx[i] >= 0)
            v[i] = x4[xbase + (long long)idx[i] * 96 + lane];
    }

    #pragma unroll
    for (int i = 0; i < 4; ++i)
        __stcs(&out4[obase + (long long)(fl + i * 4) * 96 + lane], v[i]);

    // mel_mask passthrough: 16 frames per block, threads 0..15
    if (tid < FRAMES_PER_BLOCK) {
        const int fm = b * MAXLEN + t0 + tid;
        out[OFF_MASK + fm] = mel_mask[fm] ? 1.0f : 0.0f;
    }
}

// ---------------------------------------------------------------------------
extern "C" void kernel_launch(void* const* d_in, const int* in_sizes, int n_in,
                              void* d_out, int out_size) {
    // metadata order: x, src_mask, mel_mask, duration_target, pitch_target, max_len
    const float* x        = (const float*)d_in[0];
    const int*   mel_mask = (const int*)d_in[2];     // bool stored as int32
    const int*   dur      = (const int*)d_in[3];
    float* out = (float*)d_out;

    // 1) cumsum + mel_len only (~2 us)
    k_scan<<<B_DIM, 1024>>>(dur, out);

    // 2) fused index + gather + mask: 16 frames per block, 4 float4/thread
    {
        int nblocks = B_DIM * BLOCKS_PER_BATCH;   // 16384
        k_gather<<<nblocks, 384>>>((const float4*)x, mel_mask, (float4*)out, out);
    }
}